// round 16
// baseline (speedup 1.0000x reference)
#include <cuda_runtime.h>
#include <cuda_fp16.h>
#include <cstdint>

#define N_NODES 100000
#define N_EDGES 800000
#define F 64

// ---------------- scratch (device globals; no allocation allowed) ----------
__device__ __half g_h [N_NODES * F];      // fp16 node features
__device__ __half g_y [N_NODES * F];      // fp16 y (edge-gather operand)
__device__ __half g_hN[N_NODES * F];      // fp16 mailbox means
__device__ float  g_E1[64 * 64];
__device__ __align__(16) int    g_deg[N_NODES];
__device__ __align__(16) int    g_off[N_NODES + 4];
__device__ __align__(16) int    g_cur[N_NODES];
__device__ __align__(16) float  g_invdeg[N_NODES];
__device__ float4 g_csr_w [N_EDGES];      // {si, di, rv, src-as-int-bits}

// ---------------- E1 = emb @ W1[0]^T (64x64, exact fp32) --------------------
__global__ void e1_kernel(const float* __restrict__ emb, const float* __restrict__ W1) {
    int idx = blockIdx.x * 256 + threadIdx.x;   // 16 blocks x 256 = 4096
    int n = idx >> 6, o = idx & 63;
    float s = 0.0f;
#pragma unroll
    for (int k = 0; k < 64; k += 4) {
        float4 e = *(const float4*)(emb + n * 64 + k);
        s += e.x * __ldg(&W1[o * 67 + k])     + e.y * __ldg(&W1[o * 67 + k + 1])
           + e.z * __ldg(&W1[o * 67 + k + 2]) + e.w * __ldg(&W1[o * 67 + k + 3]);
    }
    g_E1[n * 64 + o] = s;
}

// ---------------- CSR build -------------------------------------------------
__global__ void hist_kernel(const int* __restrict__ dst) {
    int e = blockIdx.x * blockDim.x + threadIdx.x;
    if (e < N_EDGES) atomicAdd(&g_deg[dst[e]], 1);
}

// also zeroes g_deg for the next graph replay (globals start zero-initialized)
__global__ void scan_kernel() {
    __shared__ int ssum[1024];
    int tid = threadIdx.x;
    const int CH = 100;
    int st = tid * CH;
    bool act = st < N_NODES;
    int s = 0;
    if (act) {
        const int4* p = (const int4*)(g_deg + st);
#pragma unroll
        for (int i = 0; i < CH / 4; i++) {
            int4 v = p[i];
            s += v.x + v.y + v.z + v.w;
        }
    }
    ssum[tid] = s;
    __syncthreads();
    for (int d = 1; d < 1024; d <<= 1) {
        int v = (tid >= d) ? ssum[tid - d] : 0;
        __syncthreads();
        ssum[tid] += v;
        __syncthreads();
    }
    int run = ssum[tid] - s;
    if (act) {
        int4* p = (int4*)(g_deg + st);
#pragma unroll 4
        for (int i = 0; i < CH / 4; i++) {
            int4 dg = p[i];
            p[i] = make_int4(0, 0, 0, 0);   // reset for next replay
            int4 off;
            float4 inv;
            off.x = run; run += dg.x; inv.x = 1.0f / (float)max(dg.x, 1);
            off.y = run; run += dg.y; inv.y = 1.0f / (float)max(dg.y, 1);
            off.z = run; run += dg.z; inv.z = 1.0f / (float)max(dg.z, 1);
            off.w = run; run += dg.w; inv.w = 1.0f / (float)max(dg.w, 1);
            ((int4*)(g_off + st))[i] = off;
            ((int4*)(g_cur + st))[i] = off;
            ((float4*)(g_invdeg + st))[i] = inv;
        }
    }
    if (tid == 1023) g_off[N_NODES] = ssum[1023];
}

__global__ void fill_kernel(const int* __restrict__ src, const int* __restrict__ dst,
                            const float* __restrict__ si, const float* __restrict__ di,
                            const float* __restrict__ rv) {
    int e = blockIdx.x * blockDim.x + threadIdx.x;
    if (e >= N_EDGES) return;
    int d = dst[e];
    int pos = atomicAdd(&g_cur[d], 1);
    g_csr_w[pos] = make_float4(si[e], di[e], rv[e], __int_as_float(src[e]));
}

// ---------------- embedding + y0 gather (both fp16) --------------------------
__global__ void embed2_kernel(const int* __restrict__ gt, const float* __restrict__ emb,
                              __half* __restrict__ h, __half* __restrict__ y) {
    int idx = blockIdx.x * blockDim.x + threadIdx.x;
    if (idx >= N_NODES * (F / 4)) return;
    int n = idx >> 4;
    int c = idx & 15;
    int t = __ldg(&gt[n]);
    float4 e  = ((const float4*)emb)[(size_t)t * 16 + c];
    float4 e1 = ((const float4*)g_E1)[(size_t)t * 16 + c];
    __half2 ha = __floats2half2_rn(e.x, e.y),  hb = __floats2half2_rn(e.z, e.w);
    __half2 ya = __floats2half2_rn(e1.x, e1.y), yb = __floats2half2_rn(e1.z, e1.w);
    uint2 hp, yp;
    hp.x = *(uint32_t*)&ha; hp.y = *(uint32_t*)&hb;
    yp.x = *(uint32_t*)&ya; yp.y = *(uint32_t*)&yb;
    *(uint2*)&h[(size_t)n * F + 4 * c] = hp;
    *(uint2*)&y[(size_t)n * F + 4 * c] = yp;
}

// ---------------- fp16 weight-split helpers ----------------------------------
__device__ __forceinline__ void splitw(float f0, float f1, uint32_t& hi, uint32_t& lo) {
    __half2 hh = __floats2half2_rn(f0, f1);
    float2 bk = __half22float2(hh);
    __half2 ll = __floats2half2_rn(f0 - bk.x, f1 - bk.y);
    hi = *(uint32_t*)&hh;
    lo = *(uint32_t*)&ll;
}

__device__ __forceinline__ uint32_t packh(float f0, float f1) {
    __half2 hh = __floats2half2_rn(f0, f1);
    return *(uint32_t*)&hh;
}

__device__ __forceinline__ void mma16816(float* d,
    uint32_t a0, uint32_t a1, uint32_t a2, uint32_t a3, uint32_t b0, uint32_t b1) {
    asm("mma.sync.aligned.m16n8k16.row.col.f32.f16.f16.f32 "
        "{%0,%1,%2,%3},{%4,%5,%6,%7},{%8,%9},{%0,%1,%2,%3};"
        : "+f"(d[0]), "+f"(d[1]), "+f"(d[2]), "+f"(d[3])
        : "r"(a0), "r"(a1), "r"(a2), "r"(a3), "r"(b0), "r"(b1));
}

// ---------------- fused persistent tensor-core GEMM kernel -------------------
// A is pure fp16 (exact; one fragment buffer). B = Wh + Wl (fp16 pair).
// Cross-GEMM state is packed to fp16 A-fragments EARLY (af[16]) so the fp32
// accumulators die before the next GEMM starts -> no spills at 3 CTAs/SM.
static const int A_FRAG_U32 = 8 * 2 * 32 * 4;   // 2048 u32 = 8KB per buffer

__device__ __forceinline__ int aoff(int w, int t, int lane) {
    return ((w * 2 + t) * 32 + lane) * 4;
}
template <int NJ>
__device__ __forceinline__ int boff(int c, int t, int j, int lane) {
    return (((c * 2 + t) * NJ + j) * 32 + lane) * 4;
}

template <int NJ>
__device__ __forceinline__ void stageB(uint32_t* sB, const float* W, int ldw, int KU, int tid) {
    for (int idx = tid; idx < NJ * 8 * KU; idx += 256) {
        int o = idx / KU, kk = idx - o * KU;
        const float* p = W + (size_t)o * ldw + 2 * kk;
        uint32_t h, l; splitw(p[0], p[1], h, l);
        int j = o >> 3, g = o & 7;
        int c = kk >> 4, r16 = kk & 15, t = r16 >> 3, rem = r16 & 7;
        int tig = rem & 3, cp = rem >> 2;
        uint32_t* q = &sB[boff<NJ>(c, t, j, g * 4 + tig)];
        q[cp] = h; q[2 + cp] = l;
    }
}

template <int K1, int K2>
__device__ __forceinline__ void prefetch_chunk(uint4* pf, int node0, int kc,
                                               const __half* __restrict__ A1,
                                               const __half* __restrict__ A2, int tid) {
#pragma unroll
    for (int s = 0; s < 2; s++) {
        int idx = tid + s * 256;          // 0..511
        int r = idx >> 2, seg = idx & 3;
        int node = node0 + r;
        int kg = kc + seg * 8;            // half index within row
        uint4 v = make_uint4(0, 0, 0, 0);
        if (node < N_NODES) {
            if (K2 == 0 || kg < K1)
                v = *(const uint4*)(A1 + (size_t)node * K1 + kg);
            else
                v = *(const uint4*)(A2 + (size_t)node * K2 + (kg - K1));
        }
        pf[s] = v;
    }
}

template <int K1, int K2, int NOUT, bool RELU1, bool WRITE1,
          bool HAS2, bool RELU2, bool WRITE2, bool HAS3, int MINB>
__global__ __launch_bounds__(256, MINB)
void tensor_kernel(const __half* __restrict__ A1, const __half* __restrict__ A2,
                   const float* __restrict__ W1, int ldw1, const float* __restrict__ bias1,
                   __half* __restrict__ out1,
                   const float* __restrict__ W2, int ldw2, const float* __restrict__ bias2,
                   __half* __restrict__ out2,
                   const float* __restrict__ W3, const float* __restrict__ bias3,
                   float* __restrict__ out3, int n_tiles) {
    constexpr int K  = K1 + K2;
    constexpr int NC = K / 32;
    constexpr int NJ = NOUT / 8;
    constexpr int B1_U32 = NC * NJ * 256;
    extern __shared__ uint32_t dsm[];
    uint32_t* sA  = dsm;
    uint32_t* sB1 = dsm + 2 * A_FRAG_U32;
    uint32_t* sB2 = sB1 + B1_U32;
    uint32_t* sB3 = sB2 + 2 * 8 * 256;   // after B2 (16KB)

    const int tid  = threadIdx.x;
    const int warp = tid >> 5;
    const int lane = tid & 31;
    const int g    = lane >> 2;
    const int tig  = lane & 3;
    const int rowA = warp * 16 + g;

    stageB<NJ>(sB1, W1, ldw1, K / 2, tid);
    if (HAS2) stageB<8>(sB2, W2, ldw2, 32, tid);
    if (HAS3) stageB<4>(sB3, W3, 64, 32, tid);

    uint4 pf[2];
    prefetch_chunk<K1, K2>(pf, blockIdx.x * 128, 0, A1, A2, tid);

    for (int tile = blockIdx.x; tile < n_tiles; tile += gridDim.x) {
        const int node0 = tile * 128;

        float d[NJ][4];
#pragma unroll
        for (int j = 0; j < NJ; j++) { d[j][0] = d[j][1] = d[j][2] = d[j][3] = 0.0f; }

        for (int c = 0; c < NC; c++) {
            uint32_t* sAb = sA + (c & 1) * A_FRAG_U32;
            // scatter raw fp16 pairs into fragment layout — no conversion
#pragma unroll
            for (int s = 0; s < 2; s++) {
                int idx = tid + s * 256;
                int r = idx >> 2, seg = idx & 3;
                uint4 v = pf[s];
                uint32_t packs[4] = {v.x, v.y, v.z, v.w};
                int w = r >> 4, rr = r & 15, b = rr >> 3, gg = rr & 7;
#pragma unroll
                for (int u = 0; u < 4; u++) {
                    int kk = seg * 4 + u;
                    int t = kk >> 3, rem = kk & 7, tg = rem & 3, cp = rem >> 2;
                    sAb[aoff(w, t, gg * 4 + tg) + (cp * 2 + b)] = packs[u];
                }
            }
            __syncthreads();   // single barrier per chunk (double buffer)

            if (c + 1 < NC)
                prefetch_chunk<K1, K2>(pf, node0, (c + 1) * 32, A1, A2, tid);
            else if (tile + gridDim.x < n_tiles)
                prefetch_chunk<K1, K2>(pf, node0 + gridDim.x * 128, 0, A1, A2, tid);

#pragma unroll
            for (int t = 0; t < 2; t++) {
                uint4 A = *(const uint4*)&sAb[aoff(warp, t, lane)];
#pragma unroll
                for (int j = 0; j < NJ; j++) {
                    uint4 B = *(const uint4*)&sB1[boff<NJ>(c, t, j, lane)];
                    mma16816(d[j], A.x, A.y, A.z, A.w, B.x, B.y);
                    mma16816(d[j], A.x, A.y, A.z, A.w, B.z, B.w);
                }
            }
        }

        // epilogue 1: bias + act, write out1, and PACK to fp16 frags (d dies here)
        uint32_t af[HAS2 ? 16 : 1];
#pragma unroll
        for (int j = 0; j < NJ; j++) {
            int c0 = 8 * j + 2 * tig;
            if (bias1) {
                float b0 = __ldg(&bias1[c0]), b1 = __ldg(&bias1[c0 + 1]);
                d[j][0] += b0; d[j][1] += b1; d[j][2] += b0; d[j][3] += b1;
            }
            if (RELU1) {
                d[j][0] = fmaxf(d[j][0], 0.0f); d[j][1] = fmaxf(d[j][1], 0.0f);
                d[j][2] = fmaxf(d[j][2], 0.0f); d[j][3] = fmaxf(d[j][3], 0.0f);
            }
            uint32_t p0 = packh(d[j][0], d[j][1]);
            uint32_t p1 = packh(d[j][2], d[j][3]);
            if (WRITE1) {
                int r0 = node0 + rowA, r1 = r0 + 8;
                if (r0 < N_NODES) *(uint32_t*)&out1[(size_t)r0 * NOUT + c0] = p0;
                if (r1 < N_NODES) *(uint32_t*)&out1[(size_t)r1 * NOUT + c0] = p1;
            }
            if (HAS2) { af[2 * j] = p0; af[2 * j + 1] = p1; }
        }

        if (HAS2) {
            float d2[8][4];
#pragma unroll
            for (int j = 0; j < 8; j++) { d2[j][0] = d2[j][1] = d2[j][2] = d2[j][3] = 0.0f; }

#pragma unroll
            for (int tt = 0; tt < 4; tt++) {
#pragma unroll
                for (int j = 0; j < 8; j++) {
                    uint4 B = *(const uint4*)&sB2[boff<8>(tt >> 1, tt & 1, j, lane)];
                    mma16816(d2[j], af[4 * tt], af[4 * tt + 1], af[4 * tt + 2], af[4 * tt + 3], B.x, B.y);
                    mma16816(d2[j], af[4 * tt], af[4 * tt + 1], af[4 * tt + 2], af[4 * tt + 3], B.z, B.w);
                }
            }

            // epilogue 2: bias + act, write out2, pack to af2 (d2 dies here)
            uint32_t af2[HAS3 ? 16 : 1];
#pragma unroll
            for (int j = 0; j < 8; j++) {
                int c0 = 8 * j + 2 * tig;
                if (bias2) {
                    float b0 = __ldg(&bias2[c0]), b1 = __ldg(&bias2[c0 + 1]);
                    d2[j][0] += b0; d2[j][1] += b1; d2[j][2] += b0; d2[j][3] += b1;
                }
                if (RELU2) {
                    d2[j][0] = fmaxf(d2[j][0], 0.0f); d2[j][1] = fmaxf(d2[j][1], 0.0f);
                    d2[j][2] = fmaxf(d2[j][2], 0.0f); d2[j][3] = fmaxf(d2[j][3], 0.0f);
                }
                uint32_t p0 = packh(d2[j][0], d2[j][1]);
                uint32_t p1 = packh(d2[j][2], d2[j][3]);
                if (WRITE2) {
                    int r0 = node0 + rowA, r1 = r0 + 8;
                    if (r0 < N_NODES) *(uint32_t*)&out2[(size_t)r0 * 64 + c0] = p0;
                    if (r1 < N_NODES) *(uint32_t*)&out2[(size_t)r1 * 64 + c0] = p1;
                }
                if (HAS3) { af2[2 * j] = p0; af2[2 * j + 1] = p1; }
            }

            // ---- GEMM3: OUT3 = D2 @ W3^T + bias3, N=32 — no barriers ----
            if (HAS3) {
                float d3[4][4];
#pragma unroll
                for (int j = 0; j < 4; j++) { d3[j][0] = d3[j][1] = d3[j][2] = d3[j][3] = 0.0f; }

#pragma unroll
                for (int tt = 0; tt < 4; tt++) {
#pragma unroll
                    for (int j = 0; j < 4; j++) {
                        uint4 B = *(const uint4*)&sB3[boff<4>(tt >> 1, tt & 1, j, lane)];
                        mma16816(d3[j], af2[4 * tt], af2[4 * tt + 1], af2[4 * tt + 2], af2[4 * tt + 3], B.x, B.y);
                        mma16816(d3[j], af2[4 * tt], af2[4 * tt + 1], af2[4 * tt + 2], af2[4 * tt + 3], B.z, B.w);
                    }
                }

                int r0 = node0 + rowA, r1 = r0 + 8;
#pragma unroll
                for (int j = 0; j < 4; j++) {
                    int c0 = 8 * j + 2 * tig;
                    float b0 = __ldg(&bias3[c0]), b1 = __ldg(&bias3[c0 + 1]);
                    float v00 = d3[j][0] + b0, v01 = d3[j][1] + b1;
                    float v10 = d3[j][2] + b0, v11 = d3[j][3] + b1;
                    if (r0 < N_NODES) *(float2*)&out3[(size_t)r0 * 32 + c0] = make_float2(v00, v01);
                    if (r1 < N_NODES) *(float2*)&out3[(size_t)r1 * 32 + c0] = make_float2(v10, v11);
                }
            }
        }
    }
}

template <int K, int NJ, bool HAS2, bool HAS3>
constexpr int smem_bytes() {
    return (2 * A_FRAG_U32 + (K / 32) * NJ * 256 +
            (HAS2 ? 2 * 8 * 256 : 0) + (HAS3 ? 2 * 4 * 256 : 0)) * 4;
}

// ---------------- edge aggregation (gather-side, depth-1 prefetch) -----------
__global__ void edge_kernel(const float* __restrict__ W1i) {
    int gid = blockIdx.x * blockDim.x + threadIdx.x;
    int node = gid >> 5;
    int lane = gid & 31;
    if (node >= N_NODES) return;

    int o0 = 2 * lane, o1 = 2 * lane + 1;
    float ax = __ldg(&W1i[o0 * 67 + 64]), ay = __ldg(&W1i[o1 * 67 + 64]);
    float bx = __ldg(&W1i[o0 * 67 + 65]), by = __ldg(&W1i[o1 * 67 + 65]);
    float cx = __ldg(&W1i[o0 * 67 + 66]), cy = __ldg(&W1i[o1 * 67 + 66]);

    float accx = 0.0f, accy = 0.0f;
    int jb = g_off[node], je = g_off[node + 1];

    float4 wN = make_float4(0, 0, 0, 0);
    if (jb < je) wN = g_csr_w[jb];
    for (int j = jb; j < je; j++) {
        float4 wv = wN;
        if (j + 1 < je) wN = g_csr_w[j + 1];
        int s = __float_as_int(wv.w);
        float2 yv = __half22float2(*(const __half2*)&g_y[(size_t)s * F + 2 * lane]);
        float tx = fmaf(ax, wv.x, fmaf(bx, wv.y, fmaf(cx, wv.z, yv.x)));
        float ty = fmaf(ay, wv.x, fmaf(by, wv.y, fmaf(cy, wv.z, yv.y)));
        tx = (tx >= 0.0f) ? tx : 0.01f * tx;
        ty = (ty >= 0.0f) ? ty : 0.01f * ty;
        accx += tx;
        accy += ty;
    }
    float id = g_invdeg[node];
    *(__half2*)&g_hN[(size_t)node * F + 2 * lane] = __floats2half2_rn(accx * id, accy * id);
}

// ---------------- launch -----------------------------------------------------
extern "C" void kernel_launch(void* const* d_in, const int* in_sizes, int n_in,
                              void* d_out, int out_size) {
    const int*   gate_type = (const int*)  d_in[0];
    const int*   src       = (const int*)  d_in[1];
    const int*   dst       = (const int*)  d_in[2];
    const float* src_idx   = (const float*)d_in[3];
    const float* dst_idx   = (const float*)d_in[4];
    const float* rev       = (const float*)d_in[5];
    const float* emb       = (const float*)d_in[6];
    const float* W1        = (const float*)d_in[7];   // [5,64,67]
    const float* W2        = (const float*)d_in[8];   // [5,64,128]
    const float* b2        = (const float*)d_in[9];   // [5,64]
    const float* Wl1       = (const float*)d_in[10];  // [64,64]
    const float* bl1       = (const float*)d_in[11];  // [64]
    const float* Wl2       = (const float*)d_in[12];  // [32,64]
    const float* bl2       = (const float*)d_in[13];  // [32]
    float*       out       = (float*)d_out;

    __half *ph, *py, *phN;
    cudaGetSymbolAddress((void**)&ph,  g_h);
    cudaGetSymbolAddress((void**)&py,  g_y);
    cudaGetSymbolAddress((void**)&phN, g_hN);

    constexpr int SM_COMB  = smem_bytes<128, 8, true, false>();   // 64KB
    constexpr int SM_COMB3 = smem_bytes<128, 8, true, true>();    // 72KB

    cudaFuncSetAttribute(
        (const void*)tensor_kernel<64, 64, 64, true, true, true, false, true, false, 3>,
        cudaFuncAttributeMaxDynamicSharedMemorySize, SM_COMB);
    cudaFuncSetAttribute(
        (const void*)tensor_kernel<64, 64, 64, true, false, true, true, false, true, 2>,
        cudaFuncAttributeMaxDynamicSharedMemorySize, SM_COMB3);

    const int TB = (N_NODES + 127) / 128;    // 782 tiles
    const int GRID_T3 = 444;                 // 148 SMs x 3 resident CTAs
    const int GRID_T2 = 296;
    const int EDGE_BLOCKS = (N_NODES * 32 + 255) / 256;

    e1_kernel<<<16, 256>>>(emb, W1);
    hist_kernel<<<(N_EDGES + 255) / 256, 256>>>(dst);
    scan_kernel<<<1, 1024>>>();
    fill_kernel<<<(N_EDGES + 255) / 256, 256>>>(src, dst, src_idx, dst_idx, rev);
    embed2_kernel<<<(N_NODES * (F / 4) + 255) / 256, 256>>>(gate_type, emb, ph, py);

    for (int i = 0; i < 4; i++) {
        const float* W1n  = W1 + (size_t)(i + 1) * 64 * 67;
        const float* W2i  = W2 + (size_t)i * 64 * 128;
        const float* b2i  = b2 + (size_t)i * 64;
        edge_kernel<<<EDGE_BLOCKS, 256>>>(W1 + (size_t)i * 64 * 67);
        // h = relu([h|hN]@W2^T + b2)  fused with  y = h @ W1next^T  (3 CTAs/SM)
        tensor_kernel<64, 64, 64, true, true, true, false, true, false, 3>
            <<<GRID_T3, 256, SM_COMB>>>(
            ph, phN, W2i, 128, b2i, ph, W1n, 67, nullptr, py,
            nullptr, nullptr, nullptr, TB);
    }

    edge_kernel<<<EDGE_BLOCKS, 256>>>(W1 + (size_t)4 * 64 * 67);
    // last combine fused with BOTH heads
    tensor_kernel<64, 64, 64, true, false, true, true, false, true, 2>
        <<<GRID_T2, 256, SM_COMB3>>>(
        ph, phN, W2 + (size_t)4 * 64 * 128, 128, b2 + 4 * 64, nullptr,
        Wl1, 64, bl1, nullptr,
        Wl2, bl2, out, TB);
}

// round 17
// speedup vs baseline: 1.0404x; 1.0404x over previous
#include <cuda_runtime.h>
#include <cuda_fp16.h>
#include <cstdint>

#define N_NODES 100000
#define N_EDGES 800000
#define F 64

// ---------------- scratch (device globals; no allocation allowed) ----------
__device__ __half g_h [N_NODES * F];      // fp16 node features
__device__ __half g_y [N_NODES * F];      // fp16 y (edge-gather operand)
__device__ __half g_hN[N_NODES * F];      // fp16 mailbox means
__device__ float  g_E1[64 * 64];
__device__ __align__(16) int    g_deg[N_NODES];
__device__ __align__(16) int    g_off[N_NODES + 4];
__device__ __align__(16) int    g_cur[N_NODES];
__device__ __align__(16) float  g_invdeg[N_NODES];
__device__ float4 g_csr_w [N_EDGES];      // {si, di, rv, src-as-int-bits}

// ---------------- fused prologue 1: E1 GEMM + degree histogram ---------------
// blocks [0,16): E1 = emb @ W1[0]^T (4096 outputs); blocks [16, 16+3125): hist
__global__ void pre_kernel(const float* __restrict__ emb, const float* __restrict__ W1,
                           const int* __restrict__ dst) {
    if (blockIdx.x < 16) {
        int idx = blockIdx.x * 256 + threadIdx.x;
        int n = idx >> 6, o = idx & 63;
        float s = 0.0f;
#pragma unroll
        for (int k = 0; k < 64; k += 4) {
            float4 e = *(const float4*)(emb + n * 64 + k);
            s += e.x * __ldg(&W1[o * 67 + k])     + e.y * __ldg(&W1[o * 67 + k + 1])
               + e.z * __ldg(&W1[o * 67 + k + 2]) + e.w * __ldg(&W1[o * 67 + k + 3]);
        }
        g_E1[n * 64 + o] = s;
    } else {
        int e = (blockIdx.x - 16) * 256 + threadIdx.x;
        if (e < N_EDGES) atomicAdd(&g_deg[dst[e]], 1);
    }
}

// also zeroes g_deg for the next graph replay (globals start zero-initialized)
__global__ void scan_kernel() {
    __shared__ int ssum[1024];
    int tid = threadIdx.x;
    const int CH = 100;
    int st = tid * CH;
    bool act = st < N_NODES;
    int s = 0;
    if (act) {
        const int4* p = (const int4*)(g_deg + st);
#pragma unroll
        for (int i = 0; i < CH / 4; i++) {
            int4 v = p[i];
            s += v.x + v.y + v.z + v.w;
        }
    }
    ssum[tid] = s;
    __syncthreads();
    for (int d = 1; d < 1024; d <<= 1) {
        int v = (tid >= d) ? ssum[tid - d] : 0;
        __syncthreads();
        ssum[tid] += v;
        __syncthreads();
    }
    int run = ssum[tid] - s;
    if (act) {
        int4* p = (int4*)(g_deg + st);
#pragma unroll 4
        for (int i = 0; i < CH / 4; i++) {
            int4 dg = p[i];
            p[i] = make_int4(0, 0, 0, 0);   // reset for next replay
            int4 off;
            float4 inv;
            off.x = run; run += dg.x; inv.x = 1.0f / (float)max(dg.x, 1);
            off.y = run; run += dg.y; inv.y = 1.0f / (float)max(dg.y, 1);
            off.z = run; run += dg.z; inv.z = 1.0f / (float)max(dg.z, 1);
            off.w = run; run += dg.w; inv.w = 1.0f / (float)max(dg.w, 1);
            ((int4*)(g_off + st))[i] = off;
            ((int4*)(g_cur + st))[i] = off;
            ((float4*)(g_invdeg + st))[i] = inv;
        }
    }
    if (tid == 1023) g_off[N_NODES] = ssum[1023];
}

// ---------------- fused prologue 2: CSR fill + embedding/y0 gather ----------
// blocks [0,3125): fill; blocks [3125, 3125+6250): embed2 (needs E1 from pre)
__global__ void fill_embed_kernel(const int* __restrict__ src, const int* __restrict__ dst,
                                  const float* __restrict__ si, const float* __restrict__ di,
                                  const float* __restrict__ rv,
                                  const int* __restrict__ gt, const float* __restrict__ emb,
                                  __half* __restrict__ h, __half* __restrict__ y) {
    if (blockIdx.x < 3125) {
        int e = blockIdx.x * 256 + threadIdx.x;
        if (e >= N_EDGES) return;
        int d = dst[e];
        int pos = atomicAdd(&g_cur[d], 1);
        g_csr_w[pos] = make_float4(si[e], di[e], rv[e], __int_as_float(src[e]));
    } else {
        int idx = (blockIdx.x - 3125) * 256 + threadIdx.x;
        if (idx >= N_NODES * (F / 4)) return;
        int n = idx >> 4;
        int c = idx & 15;
        int t = __ldg(&gt[n]);
        float4 e  = ((const float4*)emb)[(size_t)t * 16 + c];
        float4 e1 = ((const float4*)g_E1)[(size_t)t * 16 + c];
        __half2 ha = __floats2half2_rn(e.x, e.y),  hb = __floats2half2_rn(e.z, e.w);
        __half2 ya = __floats2half2_rn(e1.x, e1.y), yb = __floats2half2_rn(e1.z, e1.w);
        uint2 hp, yp;
        hp.x = *(uint32_t*)&ha; hp.y = *(uint32_t*)&hb;
        yp.x = *(uint32_t*)&ya; yp.y = *(uint32_t*)&yb;
        *(uint2*)&h[(size_t)n * F + 4 * c] = hp;
        *(uint2*)&y[(size_t)n * F + 4 * c] = yp;
    }
}

// ---------------- fp16 weight-split helpers ----------------------------------
__device__ __forceinline__ void splitw(float f0, float f1, uint32_t& hi, uint32_t& lo) {
    __half2 hh = __floats2half2_rn(f0, f1);
    float2 bk = __half22float2(hh);
    __half2 ll = __floats2half2_rn(f0 - bk.x, f1 - bk.y);
    hi = *(uint32_t*)&hh;
    lo = *(uint32_t*)&ll;
}

__device__ __forceinline__ uint32_t packh(float f0, float f1) {
    __half2 hh = __floats2half2_rn(f0, f1);
    return *(uint32_t*)&hh;
}

__device__ __forceinline__ void mma16816(float* d,
    uint32_t a0, uint32_t a1, uint32_t a2, uint32_t a3, uint32_t b0, uint32_t b1) {
    asm("mma.sync.aligned.m16n8k16.row.col.f32.f16.f16.f32 "
        "{%0,%1,%2,%3},{%4,%5,%6,%7},{%8,%9},{%0,%1,%2,%3};"
        : "+f"(d[0]), "+f"(d[1]), "+f"(d[2]), "+f"(d[3])
        : "r"(a0), "r"(a1), "r"(a2), "r"(a3), "r"(b0), "r"(b1));
}

// ---------------- fused persistent tensor-core GEMM kernel -------------------
// A is pure fp16 (exact; one fragment buffer). B = Wh + Wl (fp16 pair).
static const int A_FRAG_U32 = 8 * 2 * 32 * 4;   // 2048 u32 = 8KB per buffer

__device__ __forceinline__ int aoff(int w, int t, int lane) {
    return ((w * 2 + t) * 32 + lane) * 4;
}
template <int NJ>
__device__ __forceinline__ int boff(int c, int t, int j, int lane) {
    return (((c * 2 + t) * NJ + j) * 32 + lane) * 4;
}

template <int NJ>
__device__ __forceinline__ void stageB(uint32_t* sB, const float* W, int ldw, int KU, int tid) {
    for (int idx = tid; idx < NJ * 8 * KU; idx += 256) {
        int o = idx / KU, kk = idx - o * KU;
        const float* p = W + (size_t)o * ldw + 2 * kk;
        uint32_t h, l; splitw(p[0], p[1], h, l);
        int j = o >> 3, g = o & 7;
        int c = kk >> 4, r16 = kk & 15, t = r16 >> 3, rem = r16 & 7;
        int tig = rem & 3, cp = rem >> 2;
        uint32_t* q = &sB[boff<NJ>(c, t, j, g * 4 + tig)];
        q[cp] = h; q[2 + cp] = l;
    }
}

template <int K1, int K2>
__device__ __forceinline__ void prefetch_chunk(uint4* pf, int node0, int kc,
                                               const __half* __restrict__ A1,
                                               const __half* __restrict__ A2, int tid) {
#pragma unroll
    for (int s = 0; s < 2; s++) {
        int idx = tid + s * 256;          // 0..511
        int r = idx >> 2, seg = idx & 3;
        int node = node0 + r;
        int kg = kc + seg * 8;            // half index within row
        uint4 v = make_uint4(0, 0, 0, 0);
        if (node < N_NODES) {
            if (K2 == 0 || kg < K1)
                v = *(const uint4*)(A1 + (size_t)node * K1 + kg);
            else
                v = *(const uint4*)(A2 + (size_t)node * K2 + (kg - K1));
        }
        pf[s] = v;
    }
}

template <int K1, int K2, int NOUT, bool RELU1, bool WRITE1,
          bool HAS2, bool RELU2, bool WRITE2, bool HAS3, int MINB>
__global__ __launch_bounds__(256, MINB)
void tensor_kernel(const __half* __restrict__ A1, const __half* __restrict__ A2,
                   const float* __restrict__ W1, int ldw1, const float* __restrict__ bias1,
                   __half* __restrict__ out1,
                   const float* __restrict__ W2, int ldw2, const float* __restrict__ bias2,
                   __half* __restrict__ out2,
                   const float* __restrict__ W3, const float* __restrict__ bias3,
                   float* __restrict__ out3, int n_tiles) {
    constexpr int K  = K1 + K2;
    constexpr int NC = K / 32;
    constexpr int NJ = NOUT / 8;
    constexpr int B1_U32 = NC * NJ * 256;
    extern __shared__ uint32_t dsm[];
    uint32_t* sA  = dsm;
    uint32_t* sB1 = dsm + 2 * A_FRAG_U32;
    uint32_t* sB2 = sB1 + B1_U32;
    uint32_t* sB3 = sB2 + 2 * 8 * 256;   // after B2 (16KB)

    const int tid  = threadIdx.x;
    const int warp = tid >> 5;
    const int lane = tid & 31;
    const int g    = lane >> 2;
    const int tig  = lane & 3;
    const int rowA = warp * 16 + g;

    stageB<NJ>(sB1, W1, ldw1, K / 2, tid);
    if (HAS2) stageB<8>(sB2, W2, ldw2, 32, tid);
    if (HAS3) stageB<4>(sB3, W3, 64, 32, tid);

    uint4 pf[2];
    prefetch_chunk<K1, K2>(pf, blockIdx.x * 128, 0, A1, A2, tid);

    for (int tile = blockIdx.x; tile < n_tiles; tile += gridDim.x) {
        const int node0 = tile * 128;

        float d[NJ][4];
#pragma unroll
        for (int j = 0; j < NJ; j++) { d[j][0] = d[j][1] = d[j][2] = d[j][3] = 0.0f; }

        for (int c = 0; c < NC; c++) {
            uint32_t* sAb = sA + (c & 1) * A_FRAG_U32;
#pragma unroll
            for (int s = 0; s < 2; s++) {
                int idx = tid + s * 256;
                int r = idx >> 2, seg = idx & 3;
                uint4 v = pf[s];
                uint32_t packs[4] = {v.x, v.y, v.z, v.w};
                int w = r >> 4, rr = r & 15, b = rr >> 3, gg = rr & 7;
#pragma unroll
                for (int u = 0; u < 4; u++) {
                    int kk = seg * 4 + u;
                    int t = kk >> 3, rem = kk & 7, tg = rem & 3, cp = rem >> 2;
                    sAb[aoff(w, t, gg * 4 + tg) + (cp * 2 + b)] = packs[u];
                }
            }
            __syncthreads();   // single barrier per chunk (double buffer)

            if (c + 1 < NC)
                prefetch_chunk<K1, K2>(pf, node0, (c + 1) * 32, A1, A2, tid);
            else if (tile + gridDim.x < n_tiles)
                prefetch_chunk<K1, K2>(pf, node0 + gridDim.x * 128, 0, A1, A2, tid);

#pragma unroll
            for (int t = 0; t < 2; t++) {
                uint4 A = *(const uint4*)&sAb[aoff(warp, t, lane)];
#pragma unroll
                for (int j = 0; j < NJ; j++) {
                    uint4 B = *(const uint4*)&sB1[boff<NJ>(c, t, j, lane)];
                    mma16816(d[j], A.x, A.y, A.z, A.w, B.x, B.y);
                    mma16816(d[j], A.x, A.y, A.z, A.w, B.z, B.w);
                }
            }
        }

#pragma unroll
        for (int j = 0; j < NJ; j++) {
            int c0 = 8 * j + 2 * tig;
            if (bias1) {
                float b0 = __ldg(&bias1[c0]), b1 = __ldg(&bias1[c0 + 1]);
                d[j][0] += b0; d[j][1] += b1; d[j][2] += b0; d[j][3] += b1;
            }
            if (RELU1) {
                d[j][0] = fmaxf(d[j][0], 0.0f); d[j][1] = fmaxf(d[j][1], 0.0f);
                d[j][2] = fmaxf(d[j][2], 0.0f); d[j][3] = fmaxf(d[j][3], 0.0f);
            }
        }

        if (WRITE1) {
            int r0 = node0 + rowA, r1 = r0 + 8;
#pragma unroll
            for (int j = 0; j < NJ; j++) {
                int c0 = 8 * j + 2 * tig;
                if (r0 < N_NODES)
                    *(uint32_t*)&out1[(size_t)r0 * NOUT + c0] = packh(d[j][0], d[j][1]);
                if (r1 < N_NODES)
                    *(uint32_t*)&out1[(size_t)r1 * NOUT + c0] = packh(d[j][2], d[j][3]);
            }
        }

        if (HAS2) {
            float d2[8][4];
#pragma unroll
            for (int j = 0; j < 8; j++) { d2[j][0] = d2[j][1] = d2[j][2] = d2[j][3] = 0.0f; }

#pragma unroll
            for (int tt = 0; tt < 4; tt++) {
                uint32_t a0 = packh(d[2 * tt][0],     d[2 * tt][1]);
                uint32_t a1 = packh(d[2 * tt][2],     d[2 * tt][3]);
                uint32_t a2 = packh(d[2 * tt + 1][0], d[2 * tt + 1][1]);
                uint32_t a3 = packh(d[2 * tt + 1][2], d[2 * tt + 1][3]);
#pragma unroll
                for (int j = 0; j < 8; j++) {
                    uint4 B = *(const uint4*)&sB2[boff<8>(tt >> 1, tt & 1, j, lane)];
                    mma16816(d2[j], a0, a1, a2, a3, B.x, B.y);
                    mma16816(d2[j], a0, a1, a2, a3, B.z, B.w);
                }
            }

#pragma unroll
            for (int j = 0; j < 8; j++) {
                int c0 = 8 * j + 2 * tig;
                if (bias2) {
                    float b0 = __ldg(&bias2[c0]), b1 = __ldg(&bias2[c0 + 1]);
                    d2[j][0] += b0; d2[j][1] += b1; d2[j][2] += b0; d2[j][3] += b1;
                }
                if (RELU2) {
                    d2[j][0] = fmaxf(d2[j][0], 0.0f); d2[j][1] = fmaxf(d2[j][1], 0.0f);
                    d2[j][2] = fmaxf(d2[j][2], 0.0f); d2[j][3] = fmaxf(d2[j][3], 0.0f);
                }
            }

            if (WRITE2) {
                int r0 = node0 + rowA, r1 = r0 + 8;
#pragma unroll
                for (int j = 0; j < 8; j++) {
                    int c0 = 8 * j + 2 * tig;
                    if (r0 < N_NODES)
                        *(uint32_t*)&out2[(size_t)r0 * 64 + c0] = packh(d2[j][0], d2[j][1]);
                    if (r1 < N_NODES)
                        *(uint32_t*)&out2[(size_t)r1 * 64 + c0] = packh(d2[j][2], d2[j][3]);
                }
            }

            // ---- GEMM3: OUT3 = D2 @ W3^T + bias3, N=32 — no barriers ----
            if (HAS3) {
                float d3[4][4];
#pragma unroll
                for (int j = 0; j < 4; j++) { d3[j][0] = d3[j][1] = d3[j][2] = d3[j][3] = 0.0f; }

#pragma unroll
                for (int tt = 0; tt < 4; tt++) {
                    uint32_t a0 = packh(d2[2 * tt][0],     d2[2 * tt][1]);
                    uint32_t a1 = packh(d2[2 * tt][2],     d2[2 * tt][3]);
                    uint32_t a2 = packh(d2[2 * tt + 1][0], d2[2 * tt + 1][1]);
                    uint32_t a3 = packh(d2[2 * tt + 1][2], d2[2 * tt + 1][3]);
#pragma unroll
                    for (int j = 0; j < 4; j++) {
                        uint4 B = *(const uint4*)&sB3[boff<4>(tt >> 1, tt & 1, j, lane)];
                        mma16816(d3[j], a0, a1, a2, a3, B.x, B.y);
                        mma16816(d3[j], a0, a1, a2, a3, B.z, B.w);
                    }
                }

                int r0 = node0 + rowA, r1 = r0 + 8;
#pragma unroll
                for (int j = 0; j < 4; j++) {
                    int c0 = 8 * j + 2 * tig;
                    float b0 = __ldg(&bias3[c0]), b1 = __ldg(&bias3[c0 + 1]);
                    float v00 = d3[j][0] + b0, v01 = d3[j][1] + b1;
                    float v10 = d3[j][2] + b0, v11 = d3[j][3] + b1;
                    if (r0 < N_NODES) *(float2*)&out3[(size_t)r0 * 32 + c0] = make_float2(v00, v01);
                    if (r1 < N_NODES) *(float2*)&out3[(size_t)r1 * 32 + c0] = make_float2(v10, v11);
                }
            }
        }
    }
}

template <int K, int NJ, bool HAS2, bool HAS3>
constexpr int smem_bytes() {
    return (2 * A_FRAG_U32 + (K / 32) * NJ * 256 +
            (HAS2 ? 2 * 8 * 256 : 0) + (HAS3 ? 2 * 4 * 256 : 0)) * 4;
}

// ---------------- edge aggregation (gather-side, depth-1 prefetch) -----------
__global__ void edge_kernel(const float* __restrict__ W1i) {
    int gid = blockIdx.x * blockDim.x + threadIdx.x;
    int node = gid >> 5;
    int lane = gid & 31;
    if (node >= N_NODES) return;

    int o0 = 2 * lane, o1 = 2 * lane + 1;
    float ax = __ldg(&W1i[o0 * 67 + 64]), ay = __ldg(&W1i[o1 * 67 + 64]);
    float bx = __ldg(&W1i[o0 * 67 + 65]), by = __ldg(&W1i[o1 * 67 + 65]);
    float cx = __ldg(&W1i[o0 * 67 + 66]), cy = __ldg(&W1i[o1 * 67 + 66]);

    float accx = 0.0f, accy = 0.0f;
    int jb = g_off[node], je = g_off[node + 1];

    float4 wN = make_float4(0, 0, 0, 0);
    if (jb < je) wN = g_csr_w[jb];
    for (int j = jb; j < je; j++) {
        float4 wv = wN;
        if (j + 1 < je) wN = g_csr_w[j + 1];
        int s = __float_as_int(wv.w);
        float2 yv = __half22float2(*(const __half2*)&g_y[(size_t)s * F + 2 * lane]);
        float tx = fmaf(ax, wv.x, fmaf(bx, wv.y, fmaf(cx, wv.z, yv.x)));
        float ty = fmaf(ay, wv.x, fmaf(by, wv.y, fmaf(cy, wv.z, yv.y)));
        tx = (tx >= 0.0f) ? tx : 0.01f * tx;
        ty = (ty >= 0.0f) ? ty : 0.01f * ty;
        accx += tx;
        accy += ty;
    }
    float id = g_invdeg[node];
    *(__half2*)&g_hN[(size_t)node * F + 2 * lane] = __floats2half2_rn(accx * id, accy * id);
}

// ---------------- launch -----------------------------------------------------
extern "C" void kernel_launch(void* const* d_in, const int* in_sizes, int n_in,
                              void* d_out, int out_size) {
    const int*   gate_type = (const int*)  d_in[0];
    const int*   src       = (const int*)  d_in[1];
    const int*   dst       = (const int*)  d_in[2];
    const float* src_idx   = (const float*)d_in[3];
    const float* dst_idx   = (const float*)d_in[4];
    const float* rev       = (const float*)d_in[5];
    const float* emb       = (const float*)d_in[6];
    const float* W1        = (const float*)d_in[7];   // [5,64,67]
    const float* W2        = (const float*)d_in[8];   // [5,64,128]
    const float* b2        = (const float*)d_in[9];   // [5,64]
    const float* Wl1       = (const float*)d_in[10];  // [64,64]
    const float* bl1       = (const float*)d_in[11];  // [64]
    const float* Wl2       = (const float*)d_in[12];  // [32,64]
    const float* bl2       = (const float*)d_in[13];  // [32]
    float*       out       = (float*)d_out;

    __half *ph, *py, *phN;
    cudaGetSymbolAddress((void**)&ph,  g_h);
    cudaGetSymbolAddress((void**)&py,  g_y);
    cudaGetSymbolAddress((void**)&phN, g_hN);

    constexpr int SM_COMB  = smem_bytes<128, 8, true, false>();   // 64KB
    constexpr int SM_COMB3 = smem_bytes<128, 8, true, true>();    // 72KB

    cudaFuncSetAttribute(
        (const void*)tensor_kernel<64, 64, 64, true, true, true, false, true, false, 3>,
        cudaFuncAttributeMaxDynamicSharedMemorySize, SM_COMB);
    cudaFuncSetAttribute(
        (const void*)tensor_kernel<64, 64, 64, true, false, true, true, false, true, 2>,
        cudaFuncAttributeMaxDynamicSharedMemorySize, SM_COMB3);

    const int TB = (N_NODES + 127) / 128;    // 782 tiles
    const int GRID_T3 = 444;                 // 148 SMs x 3 resident CTAs
    const int GRID_T2 = 296;
    const int EDGE_BLOCKS = (N_NODES * 32 + 255) / 256;
    const int FILL_BLOCKS = (N_EDGES + 255) / 256;        // 3125
    const int EMB_BLOCKS  = (N_NODES * (F / 4) + 255) / 256;  // 6250

    // 1: e1 + hist, 2: scan, 3: fill + embed2, 4: edge0 (profiled slot)
    pre_kernel<<<16 + FILL_BLOCKS, 256>>>(emb, W1, dst);
    scan_kernel<<<1, 1024>>>();
    fill_embed_kernel<<<FILL_BLOCKS + EMB_BLOCKS, 256>>>(
        src, dst, src_idx, dst_idx, rev, gate_type, emb, ph, py);
    edge_kernel<<<EDGE_BLOCKS, 256>>>(W1);

    for (int i = 0; i < 4; i++) {
        const float* W1n  = W1 + (size_t)(i + 1) * 64 * 67;
        const float* W2i  = W2 + (size_t)i * 64 * 128;
        const float* b2i  = b2 + (size_t)i * 64;
        // h = relu([h|hN]@W2^T + b2)  fused with  y = h @ W1next^T  (3 CTAs/SM)
        tensor_kernel<64, 64, 64, true, true, true, false, true, false, 3>
            <<<GRID_T3, 256, SM_COMB>>>(
            ph, phN, W2i, 128, b2i, ph, W1n, 67, nullptr, py,
            nullptr, nullptr, nullptr, TB);
        edge_kernel<<<EDGE_BLOCKS, 256>>>(W1n);
    }

    // last combine fused with BOTH heads
    tensor_kernel<64, 64, 64, true, false, true, true, false, true, 2>
        <<<GRID_T2, 256, SM_COMB3>>>(
        ph, phN, W2 + (size_t)4 * 64 * 128, 128, b2 + 4 * 64, nullptr,
        Wl1, 64, bl1, nullptr,
        Wl2, bl2, out, TB);
}